// round 15
// baseline (speedup 1.0000x reference)
#include <cuda_runtime.h>
#include <cstdint>

// Problem constants
#define BATCH 32
#define TT 512
#define NINP 128
#define NHID 1024
#define KTOT 1152
#define DT_C 0.042f
#define EPSH 512.0f               // HARMONIC = N_HID * 0.5

// Geometry: 128 CTAs = 32 col-groups x 4 batch-quads; each CTA = 2 independent
// 4-batch sub-chains of 8 warps (256 threads) sharing the weight SMEM.
#define NCTA 128
#define COLS 32
#define TPB  512
#define NCH  2
#define BPCH 4
#define NWCH 8                    // warps per chain
#define KSL  144                  // k-rows per chain-warp

#define BTH (BATCH * TT * NHID)

// SMEM (floats)
#define OFF_W   0
#define SZ_W    (KTOT * COLS)             // 36864, packed [k/4][c][4rows]
#define OFF_IN  (OFF_W + SZ_W)
#define SZ_IN   (NCH * KTOT * BPCH)       // 9216: per chain [k][4b] contiguous
#define OFF_RED (OFF_IN + SZ_IN)
#define SZ_RED  (NCH * NWCH * 128)        // 2048
#define SMEM_FLOATS (OFF_RED + SZ_RED)
#define SMEM_BYTES  (SMEM_FLOATS * 4)     // 192512 B

// ---- device scratch ----
__device__ float g_xT2[4 * TT * NINP * 8];     // [bgq][t][i][8b]
__device__ float g_hyT2[2][4][NHID * 8];       // [parity][bgq][h][8b]
// one 128B line per flag; 8 chain-groups (bgq*2+s) x 32 cgrps
__device__ __align__(128) unsigned g_flags[8][32][32];

typedef unsigned long long ull;

__device__ __forceinline__ void ffma2(ull& acc, ull a, ull b) {
    asm("fma.rn.f32x2 %0, %1, %2, %0;" : "+l"(acc) : "l"(a), "l"(b));
}
__device__ __forceinline__ ull add2(ull a, ull b) {
    ull r; asm("add.rn.f32x2 %0, %1, %2;" : "=l"(r) : "l"(a), "l"(b)); return r;
}
__device__ __forceinline__ ull pack2(float lo, float hi) {
    ull r; asm("mov.b64 %0, {%1, %2};" : "=l"(r) : "f"(lo), "f"(hi)); return r;
}
__device__ __forceinline__ unsigned ld_acq(const unsigned* p) {
    unsigned v;
    asm volatile("ld.global.acquire.gpu.u32 %0, [%1];" : "=r"(v) : "l"(p));
    return v;
}
__device__ __forceinline__ void st_rel(unsigned* p, unsigned v) {
    asm volatile("st.global.release.gpu.u32 [%0], %1;" :: "l"(p), "r"(v));
}
__device__ __forceinline__ void bar_chain(int id) {
    asm volatile("bar.sync %0, 256;" :: "r"(id) : "memory");
}

// ------------------------------------------------------------------
__global__ void k_init() {
    int idx = blockIdx.x * blockDim.x + threadIdx.x;
    int stride = gridDim.x * blockDim.x;
    for (int i = idx; i < 8 * 32 * 32; i += stride)
        (&g_flags[0][0][0])[i] = 0;
    for (int i = idx; i < 4 * NHID * 8; i += stride)
        g_hyT2[0][0][i] = 0.0f;
}

__global__ void k_zero(float* __restrict__ p, int n4) {
    int idx = blockIdx.x * blockDim.x + threadIdx.x;
    int stride = gridDim.x * blockDim.x;
    float4 z = make_float4(0.f, 0.f, 0.f, 0.f);
    float4* p4 = reinterpret_cast<float4*>(p);
    for (int i = idx; i < n4; i += stride) p4[i] = z;
}

// x[b][t][i] -> g_xT2[bgq][t][i][b&7]
__global__ void k_xpose(const float* __restrict__ x) {
    int idx = blockIdx.x * blockDim.x + threadIdx.x;
    int stride = gridDim.x * blockDim.x;
    const int N = 4 * TT * NINP * 8;
    for (int o = idx; o < N; o += stride) {
        int blo = o & 7;
        int i = (o >> 3) & (NINP - 1);
        int t = (o >> 10) & (TT - 1);
        int bg = o >> 19;
        g_xT2[o] = x[((size_t)(bg * 8 + blo) * TT + t) * NINP + i];
    }
}

// ------------------------------------------------------------------
// persistent recurrent kernel: 128 CTAs x 512 threads, 2 sub-chains/CTA
// ------------------------------------------------------------------
__global__ void __launch_bounds__(TPB, 1) k_recur(
    const float* __restrict__ x2h,
    const float* __restrict__ h2h,
    const float* __restrict__ gamma,
    const float* __restrict__ eps,
    const float* __restrict__ bias,
    float* __restrict__ out)
{
    extern __shared__ float sm[];
    float* w_s  = sm + OFF_W;     // packed [kq][c][r0..r3]
    float* in_a = sm + OFF_IN;    // chain s region: [k][4b] contiguous
    float* red_a= sm + OFF_RED;   // chain s region: [w][128]

    const int tid  = threadIdx.x;
    const int wid  = tid >> 5;
    const int lane = tid & 31;
    const int s    = wid >> 3;    // chain 0/1
    const int wch  = wid & 7;     // warp within chain
    const int cgrp = blockIdx.x >> 2;
    const int bgq  = blockIdx.x & 3;
    const int cg0  = cgrp * COLS;
    const int kb   = wch * KSL;
    const int cb   = bgq * 2 + s; // chain-group id

    // --- weights: coalesced global read -> packed SMEM [k/4][c][k&3] ---
    for (int idx = tid; idx < KTOT * COLS; idx += TPB) {
        int k = idx >> 5;
        int c = idx & 31;
        float v = (k < NINP) ? x2h[(size_t)k * NHID + cg0 + c]
                             : h2h[(size_t)(k - NINP) * NHID + cg0 + c];
        w_s[((k >> 2) << 7) + (c << 2) + (k & 3)] = v;
    }

    // --- chain-local pointers ---
    float* in_c  = in_a + s * (KTOT * BPCH);
    float* red_c = red_a + s * (NWCH * 128);

    // --- update params: ut = position within chain; ut<128 does updates ---
    const int ut = tid & 255;
    const int uc = ut >> 2;
    const int ub = ut & 3;
    const int hg = cg0 + uc;
    float hy_r = 0.f, hz_r = 0.f;
    float gam = 0.f, epc = 0.f, bi = 0.f;
    if (ut < 128) {
        gam = gamma[hg];
        epc = eps[hg] * EPSH;
        bi  = bias[hg];
    }

    // --- this warp's producer flags (hy rows [kb-128, kb+144)) ---
    int p0 = 0, npf = 0;
    {
        int ke = kb + KSL;
        if (ke > NINP) {
            int h0 = ((kb > NINP) ? kb : NINP) - NINP;
            int h1 = ke - NINP - 1;
            p0 = h0 >> 5;
            npf = (h1 >> 5) - p0 + 1;   // <= 6
        }
    }
    const unsigned* myflag = &g_flags[cb][p0 + lane][0];

    const float4* xs_base = (const float4*)(g_xT2 + (size_t)bgq * (TT * NINP * 8));
    const float4* wp = (const float4*)w_s + ((kb >> 2) << 5) + lane;
    const ulonglong2* hrow = (const ulonglong2*)in_c + kb;
    float4* dstc = (float4*)in_c;

    __syncthreads();

    for (int t = 0; t < TT; t++) {
        const int p = t & 1;

        // ---- stage x rows (no cross-CTA dependency) ----
        {
            const float4* xs = xs_base + (size_t)t * (NINP * 2);
#pragma unroll
            for (int r = lane; r < KSL; r += 32) {
                int k = kb + r;
                if (k < NINP) dstc[k] = __ldg(xs + k * 2 + s);
            }
        }

        // ---- fine-grained poll: only this warp's producers ----
        if (lane < npf) {
            const unsigned want = (unsigned)t;
            while (ld_acq(myflag) < want) { }
        }
        __syncwarp();

        // ---- stage hy rows (chain's 16B half of each 32B row) ----
        {
            const float4* hy4 = (const float4*)(&g_hyT2[p][bgq][0]);
#pragma unroll
            for (int r = lane; r < KSL; r += 32) {
                int k = kb + r;
                if (k >= NINP) dstc[k] = __ldcg(hy4 + (k - NINP) * 2 + s);
            }
        }
        __syncwarp();

        // ---- GEMM: 36 fixed chunks x (4 k-rows, 1 col/lane, 4 batches) ----
        ull A0a = 0, A1a = 0, A0b = 0, A1b = 0;
#pragma unroll
        for (int ch = 0; ch < KSL / 4; ch++) {
            float4 wv = wp[ch << 5];              // lane's 4 row-weights, dense
            ulonglong2 h0 = hrow[(ch << 2) + 0];  // 16B broadcast per row
            ulonglong2 h1 = hrow[(ch << 2) + 1];
            ulonglong2 h2 = hrow[(ch << 2) + 2];
            ulonglong2 h3 = hrow[(ch << 2) + 3];
            ull w2;
            w2 = pack2(wv.x, wv.x); ffma2(A0a, w2, h0.x); ffma2(A1a, w2, h0.y);
            w2 = pack2(wv.y, wv.y); ffma2(A0b, w2, h1.x); ffma2(A1b, w2, h1.y);
            w2 = pack2(wv.z, wv.z); ffma2(A0a, w2, h2.x); ffma2(A1a, w2, h2.y);
            w2 = pack2(wv.w, wv.w); ffma2(A0b, w2, h3.x); ffma2(A1b, w2, h3.y);
        }
        ull A0 = add2(A0a, A0b);
        ull A1 = add2(A1a, A1b);

        // ---- red store: red_c[wch][c*4 + b], dense 512B per warp ----
        *(ulonglong2*)(red_c + (wch << 7) + (lane << 2)) = make_ulonglong2(A0, A1);
        bar_chain(s + 1);   // chain has observed all 32 flags >= t by here

        // ---- update: chain threads ut<128, (c=ut>>2, b=ut&3) ----
        if (ut < 128) {
            float pre = bi;
#pragma unroll
            for (int w = 0; w < NWCH; w++)
                pre += red_c[(w << 7) + ut];
            float drive = tanhf(pre);
            hz_r += DT_C * (drive - gam * hy_r - epc * hz_r);
            hy_r += DT_C * hz_r;

            __stcg(&g_hyT2[p ^ 1][bgq][hg * 8 + s * 4 + ub], hy_r);
        }
        bar_chain(s + 1);

        // ---- single-fence release to this chain's private flag line ----
        if (ut == 0) {
            __threadfence();
            st_rel(&g_flags[cb][cgrp][0], (unsigned)(t + 1));
        }

        // out stores off the inter-CTA critical path
        if (ut < 128) {
            const size_t obase = (size_t)(bgq * 8 + s * 4 + ub) * (TT * NHID)
                               + (size_t)t * NHID + hg;
            out[obase]       = hy_r;
            out[obase + BTH] = hz_r;
        }
    }
}

// ------------------------------------------------------------------
extern "C" void kernel_launch(void* const* d_in, const int* in_sizes, int n_in,
                              void* d_out, int out_size) {
    const float* x     = (const float*)d_in[0];
    const float* x2h   = (const float*)d_in[1];
    const float* h2h   = (const float*)d_in[2];
    const float* gamma = (const float*)d_in[3];
    const float* eps   = (const float*)d_in[4];
    const float* bias  = (const float*)d_in[5];
    float* out = (float*)d_out;

    cudaFuncSetAttribute(k_recur, cudaFuncAttributeMaxDynamicSharedMemorySize, SMEM_BYTES);

    k_init<<<64, 256>>>();
    k_xpose<<<512, 256>>>(x);
    // u and spike outputs are identically zero (u never leaves 0)
    k_zero<<<2048, 256>>>(out + (size_t)2 * BTH, (2 * BTH) / 4);
    k_recur<<<NCTA, TPB, SMEM_BYTES>>>(x2h, h2h, gamma, eps, bias, out);
}